// round 1
// baseline (speedup 1.0000x reference)
#include <cuda_runtime.h>
#include <math.h>

#define BB 512
#define TT 512
#define LL 126
#define NS 128
#define FILLV (-1000.0f)

// per-batch (total - real) scratch; device globals are the allowed scratch mechanism
__device__ float g_partials[BB];

// dynamic smem layout (floats):
//   [0 .. 2*NS*NS)          : float2 tet[NS*NS]   (trans, exp(trans)) pairs, 128 KB
//   [2*NS*NS .. +2*NS)      : float2 vev[NS]      (v, exp(v-a)) pairs
//   then 16 floats of reduction scratch
#define SMEM_FLOATS (2 * NS * NS + 2 * NS + 16)
#define SMEM_BYTES  (SMEM_FLOATS * sizeof(float))

extern __shared__ float s_raw[];

__global__ __launch_bounds__(128, 1) void crf_main(
    const float* __restrict__ emis,   // [B, T, L]
    const int*   __restrict__ labels, // [B, T]
    const float* __restrict__ trans)  // [NS, NS]
{
    const int b = blockIdx.x;
    const int j = threadIdx.x;   // column owned by this thread

    float2* tet = (float2*)s_raw;
    float2* vev = (float2*)(s_raw + 2 * NS * NS);
    float*  red = s_raw + 2 * NS * NS + 2 * NS;   // 16 floats
    float2* red2 = (float2*)red;                  // red2[0..3] = (S, a) partials
    // red[8..11]  = sumev partials
    // red[12..15] = real-path partials

    const float* em = emis + (size_t)b * TT * LL;
    const int*   lb = labels + b * TT;

    // ---- build (trans, exp(trans)) table in smem ----
    for (int idx = j; idx < NS * NS; idx += 128) {
        float tv = trans[idx];
        tet[idx] = make_float2(tv, __expf(tv));
    }

    // ---- real path score (parallel over t) ----
    float racc = 0.f;
    for (int t = j; t < TT; t += 128) {
        int y  = lb[t];
        int yp = (t == 0) ? LL : lb[t - 1];
        racc += em[t * LL + y] + trans[yp * NS + y];
        if (t == TT - 1) racc += trans[y * NS + (LL + 1)];
    }
    #pragma unroll
    for (int o = 16; o; o >>= 1) racc += __shfl_xor_sync(0xffffffffu, racc, o);
    __syncthreads();                       // tet ready + scratch safe
    if ((j & 31) == 0) red[12 + (j >> 5)] = racc;
    __syncthreads();
    const float real = red[12] + red[13] + red[14] + red[15];

    // ---- init scan state: v0 = E[0] ----
    float v  = (j == LL) ? 0.f : FILLV;
    float ev = (j == LL) ? 1.f : 0.f;     // exp(v - a), a = 0
    float a = 0.f, sumev = 1.f, C = 0.f;
    vev[j] = make_float2(v, ev);
    __syncthreads();

    // prefetch obs for step t=1 (emission row 0)
    float obs_next = (j < LL) ? em[j] : FILLV;

    for (int t = 1; t <= TT + 1; ++t) {
        const float obs = obs_next;
        // prefetch obs for step t+1 (hides gmem latency under the i-loop)
        if (t <= TT - 1)       obs_next = (j < LL) ? em[t * LL + j] : FILLV;
        else                   obs_next = (j == LL + 1) ? 0.f : FILLV;  // final pseudo-row

        // max-plus matvec (M_j) + exp-matvec (w_j) against previous v/ev
        float m = -3.0e38f, w = 0.f;
        #pragma unroll 8
        for (int i = 0; i < NS; ++i) {
            float2 te = tet[i * NS + j];   // conflict-free: 8B stride across lanes
            float2 ve = vev[i];            // broadcast
            m = fmaxf(m, ve.x + te.x);
            w = fmaf(ve.y, te.y, w);
        }

        // per-column contribution to S; column L (fully masked) handled exactly
        float s  = (j == LL) ? sumev : __expf(a - m) * w;
        float nv = obs + m;

        // combined reduce: S = sum(s), a_new = max(nv)
        float Sp = s, Ap = nv;
        #pragma unroll
        for (int o = 16; o; o >>= 1) {
            Sp += __shfl_xor_sync(0xffffffffu, Sp, o);
            Ap  = fmaxf(Ap, __shfl_xor_sync(0xffffffffu, Ap, o));
        }
        if ((j & 31) == 0) red2[j >> 5] = make_float2(Sp, Ap);
        __syncthreads();   // BAR_B: also separates vev reads (above) from writes (below)
        const float S = red2[0].x + red2[1].x + red2[2].x + red2[3].x;
        a = fmaxf(fmaxf(red2[0].y, red2[1].y), fmaxf(red2[2].y, red2[3].y));

        ev = __expf(nv - a);
        float Ep = ev;
        #pragma unroll
        for (int o = 16; o; o >>= 1) Ep += __shfl_xor_sync(0xffffffffu, Ep, o);
        if ((j & 31) == 0) red[8 + (j >> 5)] = Ep;
        vev[j] = make_float2(nv, ev);
        C += __logf(S);
        __syncthreads();   // BAR_C: vev + sumev partials visible for next step
        sumev = red[8] + red[9] + red[10] + red[11];
    }

    if (j == 0) {
        float total = C + a + __logf(sumev);
        g_partials[b] = total - real;
    }
}

__global__ void crf_reduce(float* __restrict__ out)
{
    __shared__ float r[16];
    const int tid = threadIdx.x;  // 512
    float x = g_partials[tid];
    #pragma unroll
    for (int o = 16; o; o >>= 1) x += __shfl_xor_sync(0xffffffffu, x, o);
    if ((tid & 31) == 0) r[tid >> 5] = x;
    __syncthreads();
    if (tid < 32) {
        float y = (tid < 16) ? r[tid] : 0.f;
        #pragma unroll
        for (int o = 8; o; o >>= 1) y += __shfl_xor_sync(0xffffffffu, y, o);
        if (tid == 0) out[0] = y;
    }
}

extern "C" void kernel_launch(void* const* d_in, const int* in_sizes, int n_in,
                              void* d_out, int out_size)
{
    const float* emis   = (const float*)d_in[0];
    const int*   labels = (const int*)d_in[1];
    const float* trans  = (const float*)d_in[2];

    cudaFuncSetAttribute(crf_main, cudaFuncAttributeMaxDynamicSharedMemorySize,
                         (int)SMEM_BYTES);

    crf_main<<<BB, 128, SMEM_BYTES>>>(emis, labels, trans);
    crf_reduce<<<1, 512>>>((float*)d_out);
}

// round 2
// speedup vs baseline: 2.4977x; 2.4977x over previous
#include <cuda_runtime.h>
#include <math.h>

#define BB 512
#define TT 512
#define LL 126
#define NS 128
#define NP 64          // i-pairs
#define BPC 4          // batches per CTA
#define NCTA (BB / BPC)
#define FILLV (-1000.0f)

__device__ float g_partials[BB];

// smem layout (float4 units):
//   tbl  : float4[NP*NS]   entry (p,j) = (t[2p][j], t[2p+1][j], et[2p][j], et[2p+1][j])   128 KB
//   vbuf : float4[BPC*NP]  entry (b,p) = (v[2p], v[2p+1], ev[2p], ev[2p+1])                4 KB
//   red  : 64 floats
#define TBL_F4  (NP * NS)
#define VBUF_F4 (BPC * NP)
#define SMEM_BYTES ((TBL_F4 + VBUF_F4) * 16 + 64 * 4)

extern __shared__ float4 s4[];

typedef unsigned long long ull;

__device__ __forceinline__ void unpack2(ull x, float& lo, float& hi) {
    unsigned a, b;
    asm("mov.b64 {%0,%1}, %2;" : "=r"(a), "=r"(b) : "l"(x));
    lo = __uint_as_float(a); hi = __uint_as_float(b);
}
__device__ __forceinline__ ull add2(ull a, ull b) {
    ull d; asm("add.rn.f32x2 %0, %1, %2;" : "=l"(d) : "l"(a), "l"(b)); return d;
}
__device__ __forceinline__ ull fma2(ull a, ull b, ull c) {
    ull d; asm("fma.rn.f32x2 %0, %1, %2, %3;" : "=l"(d) : "l"(a), "l"(b), "l"(c)); return d;
}

__global__ __launch_bounds__(128, 1) void crf_main(
    const float* __restrict__ emis,   // [B, T, L]
    const int*   __restrict__ labels, // [B, T]
    const float* __restrict__ trans)  // [NS, NS]
{
    const int j    = threadIdx.x;        // column owned by this thread
    const int warp = j >> 5;
    const int lane = j & 31;
    const int b0   = blockIdx.x * BPC;   // first global batch of this CTA

    float4* tbl   = s4;
    float4* vbuf4 = s4 + TBL_F4;
    float*  vbuf  = (float*)vbuf4;
    float*  red   = (float*)(s4 + TBL_F4 + VBUF_F4);
    float2* redSA = (float2*)red;        // [BPC][4 warps] -> 32 floats
    float*  redE  = red + 32;            // [BPC][4]
    float*  redR  = red + 48;            // [BPC][4]

    const ulonglong2* tbl64 = (const ulonglong2*)tbl;
    const ulonglong2* vb64  = (const ulonglong2*)vbuf4;

    const float* em[BPC];
    const int*   lb[BPC];
    #pragma unroll
    for (int b = 0; b < BPC; ++b) {
        em[b] = emis + (size_t)(b0 + b) * TT * LL;
        lb[b] = labels + (b0 + b) * TT;
    }

    // ---- build (t, t, et, et) pair table ----
    for (int idx = j; idx < NP * NS; idx += 128) {
        int p = idx >> 7;                 // idx % 128 == j
        float t0 = trans[(2 * p) * NS + j];
        float t1 = trans[(2 * p + 1) * NS + j];
        tbl[idx] = make_float4(t0, t1, __expf(t0), __expf(t1));
    }

    // ---- real path scores (parallel over t, per batch) ----
    float racc[BPC];
    #pragma unroll
    for (int b = 0; b < BPC; ++b) racc[b] = 0.f;
    for (int t = j; t < TT; t += 128) {
        #pragma unroll
        for (int b = 0; b < BPC; ++b) {
            int y  = lb[b][t];
            int yp = (t == 0) ? LL : lb[b][t - 1];
            racc[b] += em[b][t * LL + y] + trans[yp * NS + y];
            if (t == TT - 1) racc[b] += trans[y * NS + (LL + 1)];
        }
    }
    #pragma unroll
    for (int b = 0; b < BPC; ++b) {
        #pragma unroll
        for (int o = 16; o; o >>= 1) racc[b] += __shfl_xor_sync(0xffffffffu, racc[b], o);
    }

    // ---- init scan state (identical for all batches) ----
    {
        float v  = (j == LL) ? 0.f : FILLV;
        float ev = (j == LL) ? 1.f : 0.f;
        int p = j >> 1, lo = j & 1;
        #pragma unroll
        for (int b = 0; b < BPC; ++b) {
            vbuf[(b * NP + p) * 4 + lo]     = v;
            vbuf[(b * NP + p) * 4 + 2 + lo] = ev;
        }
    }
    __syncthreads();                       // tbl + vbuf + (scratch safe)
    if (lane == 0) {
        #pragma unroll
        for (int b = 0; b < BPC; ++b) redR[b * 4 + warp] = racc[b];
    }
    __syncthreads();
    float real[BPC];
    #pragma unroll
    for (int b = 0; b < BPC; ++b)
        real[b] = redR[b * 4] + redR[b * 4 + 1] + redR[b * 4 + 2] + redR[b * 4 + 3];

    float a[BPC], sumev[BPC], C[BPC], obs_next[BPC];
    #pragma unroll
    for (int b = 0; b < BPC; ++b) {
        a[b] = 0.f; sumev[b] = 1.f; C[b] = 0.f;
        obs_next[b] = (j < LL) ? em[b][j] : FILLV;   // emission row 0 (step t=1)
    }

    for (int t = 1; t <= TT + 1; ++t) {
        float obs[BPC];
        #pragma unroll
        for (int b = 0; b < BPC; ++b) obs[b] = obs_next[b];
        if (t <= TT - 1) {
            #pragma unroll
            for (int b = 0; b < BPC; ++b)
                obs_next[b] = (j < LL) ? em[b][t * LL + j] : FILLV;
        } else {
            #pragma unroll
            for (int b = 0; b < BPC; ++b)
                obs_next[b] = (j == LL + 1) ? 0.f : FILLV;
        }

        // ---- fused max-plus matvec + exp matvec, i-pairs, f32x2 ----
        float mA[BPC], mB[BPC];
        ull   w2[BPC];
        #pragma unroll
        for (int b = 0; b < BPC; ++b) { mA[b] = -3.0e38f; mB[b] = -3.0e38f; w2[b] = 0ull; }

        #pragma unroll 8
        for (int p = 0; p < NP; ++p) {
            ulonglong2 tp = tbl64[p * NS + j];      // .x=(t,t) .y=(et,et)
            #pragma unroll
            for (int b = 0; b < BPC; ++b) {
                ulonglong2 ve = vb64[b * NP + p];   // .x=(v,v) .y=(ev,ev)  broadcast
                ull s2 = add2(ve.x, tp.x);
                w2[b]  = fma2(ve.y, tp.y, w2[b]);
                float slo, shi; unpack2(s2, slo, shi);
                mA[b] = fmaxf(mA[b], slo);
                mB[b] = fmaxf(mB[b], shi);
            }
        }

        float m[BPC], nv[BPC], Sp[BPC], Ap[BPC];
        #pragma unroll
        for (int b = 0; b < BPC; ++b) {
            m[b] = fmaxf(mA[b], mB[b]);
            float wlo, whi; unpack2(w2[b], wlo, whi);
            float w = wlo + whi;
            // column L (fully masked) contributes exactly sumev
            Sp[b] = (j == LL) ? sumev[b] : __expf(a[b] - m[b]) * w;
            nv[b] = obs[b] + m[b];
            Ap[b] = nv[b];
        }
        #pragma unroll
        for (int o = 16; o; o >>= 1) {
            #pragma unroll
            for (int b = 0; b < BPC; ++b) {
                Sp[b] += __shfl_xor_sync(0xffffffffu, Sp[b], o);
                Ap[b]  = fmaxf(Ap[b], __shfl_xor_sync(0xffffffffu, Ap[b], o));
            }
        }
        if (lane == 0) {
            #pragma unroll
            for (int b = 0; b < BPC; ++b) redSA[b * 4 + warp] = make_float2(Sp[b], Ap[b]);
        }
        __syncthreads();                  // BAR1: vbuf reads done, reductions ready

        float Ep[BPC];
        {
            int p = j >> 1, lo = j & 1;
            #pragma unroll
            for (int b = 0; b < BPC; ++b) {
                float2 r0 = redSA[b * 4], r1 = redSA[b * 4 + 1],
                       r2 = redSA[b * 4 + 2], r3 = redSA[b * 4 + 3];
                float S = r0.x + r1.x + r2.x + r3.x;
                a[b] = fmaxf(fmaxf(r0.y, r1.y), fmaxf(r2.y, r3.y));
                C[b] += __logf(S);
                float ev = __expf(nv[b] - a[b]);
                vbuf[(b * NP + p) * 4 + lo]     = nv[b];
                vbuf[(b * NP + p) * 4 + 2 + lo] = ev;
                Ep[b] = ev;
            }
        }
        #pragma unroll
        for (int o = 16; o; o >>= 1) {
            #pragma unroll
            for (int b = 0; b < BPC; ++b) Ep[b] += __shfl_xor_sync(0xffffffffu, Ep[b], o);
        }
        if (lane == 0) {
            #pragma unroll
            for (int b = 0; b < BPC; ++b) redE[b * 4 + warp] = Ep[b];
        }
        __syncthreads();                  // BAR2: vbuf + sumev visible for next step
        #pragma unroll
        for (int b = 0; b < BPC; ++b)
            sumev[b] = redE[b * 4] + redE[b * 4 + 1] + redE[b * 4 + 2] + redE[b * 4 + 3];
    }

    if (j == 0) {
        #pragma unroll
        for (int b = 0; b < BPC; ++b) {
            float total = C[b] + a[b] + __logf(sumev[b]);
            g_partials[b0 + b] = total - real[b];
        }
    }
}

__global__ void crf_reduce(float* __restrict__ out)
{
    __shared__ float r[16];
    const int tid = threadIdx.x;  // 512
    float x = g_partials[tid];
    #pragma unroll
    for (int o = 16; o; o >>= 1) x += __shfl_xor_sync(0xffffffffu, x, o);
    if ((tid & 31) == 0) r[tid >> 5] = x;
    __syncthreads();
    if (tid < 32) {
        float y = (tid < 16) ? r[tid] : 0.f;
        #pragma unroll
        for (int o = 8; o; o >>= 1) y += __shfl_xor_sync(0xffffffffu, y, o);
        if (tid == 0) out[0] = y;
    }
}

extern "C" void kernel_launch(void* const* d_in, const int* in_sizes, int n_in,
                              void* d_out, int out_size)
{
    const float* emis   = (const float*)d_in[0];
    const int*   labels = (const int*)d_in[1];
    const float* trans  = (const float*)d_in[2];

    cudaFuncSetAttribute(crf_main, cudaFuncAttributeMaxDynamicSharedMemorySize,
                         (int)SMEM_BYTES);

    crf_main<<<NCTA, 128, SMEM_BYTES>>>(emis, labels, trans);
    crf_reduce<<<1, 512>>>((float*)d_out);
}